// round 1
// baseline (speedup 1.0000x reference)
#include <cuda_runtime.h>
#include <math.h>

#define B_  2
#define S_  2048
#define D_  1024
#define H_  16
#define DK_ 64
#define M_  (B_*S_)   // 4096

// Scratch (allocation-free rule: device globals).
__device__ float g_q[(size_t)B_*H_*S_*DK_];     // [B,H,S,DK]
__device__ float g_k[(size_t)B_*H_*S_*DK_];
__device__ float g_v[(size_t)B_*H_*S_*DK_];
__device__ float g_attn[(size_t)M_*D_];         // [B,S,D]

// C[m,n] = sum_k A[m,k] * W[n,k] + bias[n]
// LAYOUT 0: C flat [M, D].  LAYOUT 1: write to head-split [B,H,S,DK].
template<int LAYOUT>
__global__ __launch_bounds__(256) void gemm_nt(const float* __restrict__ A,
                                               const float* __restrict__ W,
                                               const float* __restrict__ bias,
                                               float* __restrict__ C)
{
    __shared__ float As[16][64];
    __shared__ float Bs[16][64];
    const int tid = threadIdx.x;
    const int ty = tid >> 4, tx = tid & 15;
    const int m0 = blockIdx.x * 64, n0 = blockIdx.y * 64;
    const int lrow = tid >> 2, lc4 = tid & 3;
    const float* Ap = A + (size_t)(m0 + lrow) * D_ + lc4 * 4;
    const float* Wp = W + (size_t)(n0 + lrow) * D_ + lc4 * 4;

    float acc[4][4] = {};
    for (int kt = 0; kt < D_; kt += 16) {
        const float4 av = *(const float4*)(Ap + kt);
        const float4 bv = *(const float4*)(Wp + kt);
        __syncthreads();
        As[lc4*4+0][lrow] = av.x; As[lc4*4+1][lrow] = av.y;
        As[lc4*4+2][lrow] = av.z; As[lc4*4+3][lrow] = av.w;
        Bs[lc4*4+0][lrow] = bv.x; Bs[lc4*4+1][lrow] = bv.y;
        Bs[lc4*4+2][lrow] = bv.z; Bs[lc4*4+3][lrow] = bv.w;
        __syncthreads();
        #pragma unroll
        for (int k = 0; k < 16; k++) {
            const float4 a4 = *(const float4*)(&As[k][ty*4]);
            const float4 b4 = *(const float4*)(&Bs[k][tx*4]);
            const float a[4] = {a4.x, a4.y, a4.z, a4.w};
            const float b[4] = {b4.x, b4.y, b4.z, b4.w};
            #pragma unroll
            for (int i = 0; i < 4; i++)
                #pragma unroll
                for (int j = 0; j < 4; j++)
                    acc[i][j] = fmaf(a[i], b[j], acc[i][j]);
        }
    }

    #pragma unroll
    for (int i = 0; i < 4; i++) {
        const int m = m0 + ty*4 + i;
        #pragma unroll
        for (int j = 0; j < 4; j++) {
            const int n = n0 + tx*4 + j;
            const float v = acc[i][j] + bias[n];
            if (LAYOUT == 0) {
                C[(size_t)m * D_ + n] = v;
            } else {
                const int bb = m >> 11, ss = m & (S_-1);
                const int hh = n >> 6,  dk = n & 63;
                C[(((size_t)bb*H_ + hh)*S_ + ss)*DK_ + dk] = v;
            }
        }
    }
}

// Flash attention per (b,h): 64-query tiles, streaming over 64-key tiles.
// 256 threads: thread (ty,tx) owns rows ty*4..+3 and cols/out-dims tx*4..+3.
__global__ __launch_bounds__(256) void attn_kernel()
{
    extern __shared__ float sm[];
    float* sQ = sm;                 // [64][68]
    float* sK = sm + 64*68;         // [64][68]
    float* sV = sm + 2*64*68;       // [64][68]
    float* sP = sm + 3*64*68;       // [64][65]

    const int tid = threadIdx.x;
    const int ty = tid >> 4, tx = tid & 15;
    const int h = blockIdx.y, b = blockIdx.z;
    const size_t bh_off = ((size_t)b * H_ + h) * S_ * DK_;
    const float* qg = g_q + bh_off;
    const float* kg = g_k + bh_off;
    const float* vg = g_v + bh_off;
    const int r0 = blockIdx.x * 64;

    // Load Q tile once (coalesced float4).
    #pragma unroll
    for (int it = 0; it < 4; it++) {
        const int idx = tid + it*256;
        const int rr = idx >> 4, d4 = idx & 15;
        *(float4*)(sQ + rr*68 + d4*4) =
            *(const float4*)(qg + (size_t)(r0+rr)*DK_ + d4*4);
    }

    float mreg[4], lreg[4], o[4][4];
    #pragma unroll
    for (int i = 0; i < 4; i++) {
        mreg[i] = -1e30f; lreg[i] = 0.f;
        #pragma unroll
        for (int j = 0; j < 4; j++) o[i][j] = 0.f;
    }

    for (int t = 0; t < S_/64; t++) {
        __syncthreads();   // protect sK/sV/sP from previous iteration's readers
        #pragma unroll
        for (int it = 0; it < 4; it++) {
            const int idx = tid + it*256;
            const int rr = idx >> 4, d4 = idx & 15;
            *(float4*)(sK + rr*68 + d4*4) =
                *(const float4*)(kg + (size_t)(t*64+rr)*DK_ + d4*4);
            *(float4*)(sV + rr*68 + d4*4) =
                *(const float4*)(vg + (size_t)(t*64+rr)*DK_ + d4*4);
        }
        __syncthreads();

        // Scores: s[i][j] = q_row(ty*4+i) . k_row(tx*4+j)
        float s[4][4] = {};
        #pragma unroll
        for (int d4 = 0; d4 < 16; d4++) {
            float4 q4[4], k4[4];
            #pragma unroll
            for (int i = 0; i < 4; i++)
                q4[i] = *(const float4*)(sQ + (ty*4+i)*68 + d4*4);
            #pragma unroll
            for (int j = 0; j < 4; j++)
                k4[j] = *(const float4*)(sK + (tx*4+j)*68 + d4*4);
            #pragma unroll
            for (int i = 0; i < 4; i++)
                #pragma unroll
                for (int j = 0; j < 4; j++) {
                    s[i][j] = fmaf(q4[i].x, k4[j].x, s[i][j]);
                    s[i][j] = fmaf(q4[i].y, k4[j].y, s[i][j]);
                    s[i][j] = fmaf(q4[i].z, k4[j].z, s[i][j]);
                    s[i][j] = fmaf(q4[i].w, k4[j].w, s[i][j]);
                }
        }

        // Online softmax. Row stats reduced across the 16 tx lanes (xor 1..8
        // stays inside the half-warp that owns a row group).
        #pragma unroll
        for (int i = 0; i < 4; i++) {
            float mx = -1e30f;
            #pragma unroll
            for (int j = 0; j < 4; j++) { s[i][j] *= 0.125f; mx = fmaxf(mx, s[i][j]); }
            #pragma unroll
            for (int off = 1; off < 16; off <<= 1)
                mx = fmaxf(mx, __shfl_xor_sync(0xffffffffu, mx, off));
            const float mnew = fmaxf(mreg[i], mx);
            const float corr = __expf(mreg[i] - mnew);
            mreg[i] = mnew;
            float ls = 0.f;
            #pragma unroll
            for (int j = 0; j < 4; j++) { s[i][j] = __expf(s[i][j] - mnew); ls += s[i][j]; }
            #pragma unroll
            for (int off = 1; off < 16; off <<= 1)
                ls += __shfl_xor_sync(0xffffffffu, ls, off);
            lreg[i] = lreg[i]*corr + ls;
            #pragma unroll
            for (int j = 0; j < 4; j++) {
                o[i][j] *= corr;
                sP[(ty*4+i)*65 + tx*4 + j] = s[i][j];
            }
        }
        __syncthreads();

        // PV accumulate: o[i][jj] += sum_c P[row][c] * V[c][tx*4+jj]
        #pragma unroll 4
        for (int c = 0; c < 64; c++) {
            const float4 v4 = *(const float4*)(sV + c*68 + tx*4);
            float p[4];
            #pragma unroll
            for (int i = 0; i < 4; i++) p[i] = sP[(ty*4+i)*65 + c];
            #pragma unroll
            for (int i = 0; i < 4; i++) {
                o[i][0] = fmaf(p[i], v4.x, o[i][0]);
                o[i][1] = fmaf(p[i], v4.y, o[i][1]);
                o[i][2] = fmaf(p[i], v4.z, o[i][2]);
                o[i][3] = fmaf(p[i], v4.w, o[i][3]);
            }
        }
    }

    // Epilogue: normalize and write [B,S,H*DK] (matches transpose+reshape).
    #pragma unroll
    for (int i = 0; i < 4; i++) {
        const float inv = 1.0f / lreg[i];
        const int srow = r0 + ty*4 + i;
        float* outp = g_attn + ((size_t)b*S_ + srow)*D_ + h*DK_ + tx*4;
        outp[0] = o[i][0]*inv; outp[1] = o[i][1]*inv;
        outp[2] = o[i][2]*inv; outp[3] = o[i][3]*inv;
    }
}

extern "C" void kernel_launch(void* const* d_in, const int* in_sizes, int n_in,
                              void* d_out, int out_size)
{
    (void)in_sizes; (void)n_in; (void)out_size;
    const float* Q  = (const float*)d_in[0];
    const float* K  = (const float*)d_in[1];
    const float* V  = (const float*)d_in[2];
    const float* Wq = (const float*)d_in[3];
    const float* bq = (const float*)d_in[4];
    const float* Wk = (const float*)d_in[5];
    const float* bk = (const float*)d_in[6];
    const float* Wv = (const float*)d_in[7];
    const float* bv = (const float*)d_in[8];
    const float* Wo = (const float*)d_in[9];
    const float* bo = (const float*)d_in[10];
    float* out = (float*)d_out;

    float *qp, *kp, *vp, *ap;
    cudaGetSymbolAddress((void**)&qp, g_q);
    cudaGetSymbolAddress((void**)&kp, g_k);
    cudaGetSymbolAddress((void**)&vp, g_v);
    cudaGetSymbolAddress((void**)&ap, g_attn);

    const dim3 gg(M_/64, D_/64);   // 64 x 16
    gemm_nt<1><<<gg, 256>>>(Q, Wq, bq, qp);
    gemm_nt<1><<<gg, 256>>>(K, Wk, bk, kp);
    gemm_nt<1><<<gg, 256>>>(V, Wv, bv, vp);

    const int smem = (3*64*68 + 64*65) * (int)sizeof(float);  // 68864 B
    cudaFuncSetAttribute(attn_kernel,
                         cudaFuncAttributeMaxDynamicSharedMemorySize, smem);
    attn_kernel<<<dim3(S_/64, H_, B_), 256, smem>>>();

    gemm_nt<0><<<gg, 256>>>(ap, Wo, bo, out);
}

// round 3
// speedup vs baseline: 2.0389x; 2.0389x over previous
#include <cuda_runtime.h>
#include <math.h>
#include <stdint.h>

#define B_  2
#define S_  2048
#define D_  1024
#define H_  16
#define DK_ 64
#define M_  (B_*S_)   // 4096

// ---------------- scratch (allocation-free rule: device globals) -------------
__device__ float g_q[(size_t)B_*H_*S_*DK_];     // [B,H,S,DK]
__device__ float g_k[(size_t)B_*H_*S_*DK_];
__device__ float g_v[(size_t)B_*H_*S_*DK_];
__device__ float g_attn[(size_t)M_*D_];         // [B,S,D]

// ---------------- helpers -----------------------------------------------------
__device__ __forceinline__ uint32_t smem_to_u32(const void* p) {
    uint32_t a;
    asm("{ .reg .u64 t; cvta.to.shared.u64 t, %1; cvt.u32.u64 %0, t; }"
        : "=r"(a) : "l"(p));
    return a;
}
__device__ __forceinline__ void cp_async16(uint32_t dst, const void* src) {
    asm volatile("cp.async.ca.shared.global [%0], [%1], 16;" :: "r"(dst), "l"(src));
}
#define CP_COMMIT() asm volatile("cp.async.commit_group;" ::: "memory")
#define CP_WAIT(n)  asm volatile("cp.async.wait_group %0;" :: "n"(n) : "memory")

// split fp32 into tf32 hi + tf32(lo) for 3xTF32
__device__ __forceinline__ void tf32_split(float v, uint32_t& hi, uint32_t& lo) {
    uint32_t h;
    asm("cvt.rna.tf32.f32 %0, %1;" : "=r"(h) : "f"(v));
    float l = v - __uint_as_float(h);
    uint32_t lb;
    asm("cvt.rna.tf32.f32 %0, %1;" : "=r"(lb) : "f"(l));
    hi = h; lo = lb;
}
__device__ __forceinline__ uint32_t tf32_of(float v) {
    uint32_t h;
    asm("cvt.rna.tf32.f32 %0, %1;" : "=r"(h) : "f"(v));
    return h;
}

// D += A(16x8 row) * B(8x8 col);  tf32 inputs, f32 acc
__device__ __forceinline__ void mma_tf32(float* d, const uint32_t* a, const uint32_t* b) {
    asm volatile("mma.sync.aligned.m16n8k8.row.col.f32.tf32.tf32.f32 "
        "{%0,%1,%2,%3}, {%4,%5,%6,%7}, {%8,%9}, {%0,%1,%2,%3};"
        : "+f"(d[0]), "+f"(d[1]), "+f"(d[2]), "+f"(d[3])
        : "r"(a[0]), "r"(a[1]), "r"(a[2]), "r"(a[3]), "r"(b[0]), "r"(b[1]));
}

// ---------------- 3xTF32 mma GEMM: C = A @ W^T + bias ------------------------
// A [4096,1024], W [1024,1024] row-major. CTA 128x128, K-chunk 32, cp.async x2.
// 8 warps as 4(M) x 2(N); warp tile 32x64 -> MT=2, NT=8 m16n8 tiles.
#define GSTR 36   // smem row stride (32 + 4 pad) floats
#define GEMM_SMEM_BYTES (4*128*GSTR*4)   // 2 stages x (A+B) = 73728

template<int LAYOUT>
__global__ __launch_bounds__(256) void gemm_mma(const float* __restrict__ A,
                                                const float* __restrict__ W,
                                                const float* __restrict__ bias,
                                                float* __restrict__ C)
{
    extern __shared__ float smg[];
    float* As = smg;                  // [2][128][36]
    float* Bs = smg + 2*128*GSTR;     // [2][128][36]
    const int tid = threadIdx.x, lane = tid & 31, wid = tid >> 5;
    const int g = lane >> 2, c = lane & 3;
    const int wm = (wid & 3) * 32, wn = (wid >> 2) * 64;
    const int m0 = blockIdx.x * 128, n0 = blockIdx.y * 128;
    const uint32_t sA = smem_to_u32(As), sB = smem_to_u32(Bs);

    float acc[2][8][4] = {};

    // prologue: stage 0
    #pragma unroll
    for (int i = 0; i < 4; i++) {
        const int idx = tid + i*256, row = idx >> 3, c4 = idx & 7;
        cp_async16(sA + (uint32_t)((row*GSTR + c4*4)*4),
                   A + (size_t)(m0+row)*D_ + c4*4);
        cp_async16(sB + (uint32_t)((row*GSTR + c4*4)*4),
                   W + (size_t)(n0+row)*D_ + c4*4);
    }
    CP_COMMIT();

    for (int ch = 0; ch < D_/32; ch++) {
        const int st = ch & 1;
        if (ch < D_/32 - 1) {
            const int st2 = st ^ 1, kt = (ch+1)*32;
            #pragma unroll
            for (int i = 0; i < 4; i++) {
                const int idx = tid + i*256, row = idx >> 3, c4 = idx & 7;
                cp_async16(sA + (uint32_t)(((st2*128+row)*GSTR + c4*4)*4),
                           A + (size_t)(m0+row)*D_ + kt + c4*4);
                cp_async16(sB + (uint32_t)(((st2*128+row)*GSTR + c4*4)*4),
                           W + (size_t)(n0+row)*D_ + kt + c4*4);
            }
            CP_COMMIT();
            CP_WAIT(1);
        } else {
            CP_WAIT(0);
        }
        __syncthreads();

        const float* Ast = As + st*128*GSTR;
        const float* Bst = Bs + st*128*GSTR;
        #pragma unroll
        for (int ks = 0; ks < 4; ks++) {
            const int k8 = ks * 8;
            uint32_t ah[2][4], al[2][4];
            #pragma unroll
            for (int mt = 0; mt < 2; mt++)
                #pragma unroll
                for (int e = 0; e < 4; e++) {
                    const int row = wm + mt*16 + g + (e & 1)*8;
                    const int col = k8 + c + (e >> 1)*4;
                    tf32_split(Ast[row*GSTR + col], ah[mt][e], al[mt][e]);
                }
            #pragma unroll
            for (int nt = 0; nt < 8; nt++) {
                uint32_t bh[2], bl[2];
                #pragma unroll
                for (int e = 0; e < 2; e++) {
                    const int n = wn + nt*8 + g;
                    tf32_split(Bst[n*GSTR + k8 + c + e*4], bh[e], bl[e]);
                }
                #pragma unroll
                for (int mt = 0; mt < 2; mt++) {
                    mma_tf32(acc[mt][nt], ah[mt], bh);
                    mma_tf32(acc[mt][nt], ah[mt], bl);
                    mma_tf32(acc[mt][nt], al[mt], bh);
                }
            }
        }
        __syncthreads();
    }

    // epilogue: direct float2 stores + bias
    #pragma unroll
    for (int mt = 0; mt < 2; mt++)
        #pragma unroll
        for (int half = 0; half < 2; half++) {
            const int m = m0 + wm + mt*16 + g + half*8;
            #pragma unroll
            for (int nt = 0; nt < 8; nt++) {
                const int n = n0 + wn + nt*8 + c*2;
                float2 v;
                v.x = acc[mt][nt][half*2+0] + bias[n];
                v.y = acc[mt][nt][half*2+1] + bias[n+1];
                if (LAYOUT == 0) {
                    *(float2*)(C + (size_t)m*D_ + n) = v;
                } else {
                    const int bb = m >> 11, ss = m & (S_-1);
                    const int hh = n >> 6,  dk = n & 63;
                    *(float2*)(C + (((size_t)bb*H_ + hh)*S_ + ss)*DK_ + dk) = v;
                }
            }
        }
}

// ---------------- 3xTF32 mma flash attention ---------------------------------
// Per (b,h): Q-tile 128 rows, K-tile 64. 8 warps, each owns 16 Q rows.
// Q/K/V pre-split hi/lo in smem; P re-fragmented through smem.
#define QSTR 68   // 64 + 4 pad
#define VSTR 72   // 64 + 8 pad (distinct banks for V's k-major frag reads)
// floats: Qh/Ql 128*68*2, Kh/Kl 64*68*2, Vh/Vl 64*72*2, Ps 128*68
#define ATTN_SMEM_FLOATS (2*128*QSTR + 2*64*QSTR + 2*64*VSTR + 128*QSTR)
#define ATTN_SMEM_BYTES (ATTN_SMEM_FLOATS*4)   // 176128

__global__ __launch_bounds__(256) void attn_mma()
{
    extern __shared__ float sma[];
    float* Qh = sma;
    float* Ql = Qh + 128*QSTR;
    float* Kh = Ql + 128*QSTR;
    float* Kl = Kh + 64*QSTR;
    float* Vh = Kl + 64*QSTR;
    float* Vl = Vh + 64*VSTR;
    float* Ps = Vl + 64*VSTR;

    const int tid = threadIdx.x, lane = tid & 31, wid = tid >> 5;
    const int g = lane >> 2, c = lane & 3;
    const int wr = wid * 16;
    const int h = blockIdx.y, b = blockIdx.z;
    const int q0 = blockIdx.x * 128;
    const size_t bh_off = ((size_t)b*H_ + h) * S_ * DK_;
    const float* qg = g_q + bh_off;
    const float* kg = g_k + bh_off;
    const float* vg = g_v + bh_off;

    // load Q tile 128x64, pre-split hi/lo
    #pragma unroll
    for (int i = 0; i < 8; i++) {
        const int idx = tid + i*256;
        const int row = idx >> 4, d4 = idx & 15;
        const float4 v = *(const float4*)(qg + (size_t)(q0+row)*DK_ + d4*4);
        float4 hv, lv; uint32_t hb, lb;
        tf32_split(v.x, hb, lb); hv.x = __uint_as_float(hb); lv.x = __uint_as_float(lb);
        tf32_split(v.y, hb, lb); hv.y = __uint_as_float(hb); lv.y = __uint_as_float(lb);
        tf32_split(v.z, hb, lb); hv.z = __uint_as_float(hb); lv.z = __uint_as_float(lb);
        tf32_split(v.w, hb, lb); hv.w = __uint_as_float(hb); lv.w = __uint_as_float(lb);
        *(float4*)(Qh + row*QSTR + d4*4) = hv;
        *(float4*)(Ql + row*QSTR + d4*4) = lv;
    }

    float o[8][4] = {};
    float m0r = -1e30f, m1r = -1e30f, l0 = 0.f, l1 = 0.f;

    for (int t = 0; t < S_/64; t++) {
        __syncthreads();   // protect K/V/P from previous iteration's readers
        #pragma unroll
        for (int i = 0; i < 4; i++) {
            const int idx = tid + i*256;
            const int row = idx >> 4, d4 = idx & 15;
            const float4 kv = *(const float4*)(kg + (size_t)(t*64+row)*DK_ + d4*4);
            const float4 vv = *(const float4*)(vg + (size_t)(t*64+row)*DK_ + d4*4);
            float4 hv, lv; uint32_t hb, lb;
            tf32_split(kv.x, hb, lb); hv.x = __uint_as_float(hb); lv.x = __uint_as_float(lb);
            tf32_split(kv.y, hb, lb); hv.y = __uint_as_float(hb); lv.y = __uint_as_float(lb);
            tf32_split(kv.z, hb, lb); hv.z = __uint_as_float(hb); lv.z = __uint_as_float(lb);
            tf32_split(kv.w, hb, lb); hv.w = __uint_as_float(hb); lv.w = __uint_as_float(lb);
            *(float4*)(Kh + row*QSTR + d4*4) = hv;
            *(float4*)(Kl + row*QSTR + d4*4) = lv;
            tf32_split(vv.x, hb, lb); hv.x = __uint_as_float(hb); lv.x = __uint_as_float(lb);
            tf32_split(vv.y, hb, lb); hv.y = __uint_as_float(hb); lv.y = __uint_as_float(lb);
            tf32_split(vv.z, hb, lb); hv.z = __uint_as_float(hb); lv.z = __uint_as_float(lb);
            tf32_split(vv.w, hb, lb); hv.w = __uint_as_float(hb); lv.w = __uint_as_float(lb);
            *(float4*)(Vh + row*VSTR + d4*4) = hv;
            *(float4*)(Vl + row*VSTR + d4*4) = lv;
        }
        __syncthreads();

        // ---- S = (Q K^T) / 8 ------------------------------------------------
        float s[8][4] = {};
        #pragma unroll
        for (int ks = 0; ks < 8; ks++) {
            const int k8 = ks * 8;
            uint32_t ah[4], al[4];
            #pragma unroll
            for (int e = 0; e < 4; e++) {
                const int row = wr + g + (e & 1)*8;
                const int col = k8 + c + (e >> 1)*4;
                ah[e] = __float_as_uint(Qh[row*QSTR + col]);
                al[e] = __float_as_uint(Ql[row*QSTR + col]);
            }
            #pragma unroll
            for (int nt = 0; nt < 8; nt++) {
                uint32_t bh[2], bl[2];
                #pragma unroll
                for (int e = 0; e < 2; e++) {
                    const int n = nt*8 + g;
                    bh[e] = __float_as_uint(Kh[n*QSTR + k8 + c + e*4]);
                    bl[e] = __float_as_uint(Kl[n*QSTR + k8 + c + e*4]);
                }
                mma_tf32(s[nt], ah, bh);
                mma_tf32(s[nt], ah, bl);
                mma_tf32(s[nt], al, bh);
            }
        }

        // ---- online softmax (rows g and g+8, stats across 4 c-lanes) --------
        float mx0 = -1e30f, mx1 = -1e30f;
        #pragma unroll
        for (int nt = 0; nt < 8; nt++) {
            s[nt][0] *= 0.125f; s[nt][1] *= 0.125f;
            s[nt][2] *= 0.125f; s[nt][3] *= 0.125f;
            mx0 = fmaxf(mx0, fmaxf(s[nt][0], s[nt][1]));
            mx1 = fmaxf(mx1, fmaxf(s[nt][2], s[nt][3]));
        }
        mx0 = fmaxf(mx0, __shfl_xor_sync(0xffffffffu, mx0, 1));
        mx0 = fmaxf(mx0, __shfl_xor_sync(0xffffffffu, mx0, 2));
        mx1 = fmaxf(mx1, __shfl_xor_sync(0xffffffffu, mx1, 1));
        mx1 = fmaxf(mx1, __shfl_xor_sync(0xffffffffu, mx1, 2));
        const float mn0 = fmaxf(m0r, mx0), mn1 = fmaxf(m1r, mx1);
        const float cr0 = __expf(m0r - mn0), cr1 = __expf(m1r - mn1);
        m0r = mn0; m1r = mn1;
        float ls0 = 0.f, ls1 = 0.f;
        #pragma unroll
        for (int nt = 0; nt < 8; nt++) {
            s[nt][0] = __expf(s[nt][0] - mn0); s[nt][1] = __expf(s[nt][1] - mn0);
            s[nt][2] = __expf(s[nt][2] - mn1); s[nt][3] = __expf(s[nt][3] - mn1);
            ls0 += s[nt][0] + s[nt][1];
            ls1 += s[nt][2] + s[nt][3];
            o[nt][0] *= cr0; o[nt][1] *= cr0;
            o[nt][2] *= cr1; o[nt][3] *= cr1;
            *(float2*)(Ps + (wr+g)*QSTR + nt*8 + c*2)   = make_float2(s[nt][0], s[nt][1]);
            *(float2*)(Ps + (wr+g+8)*QSTR + nt*8 + c*2) = make_float2(s[nt][2], s[nt][3]);
        }
        ls0 += __shfl_xor_sync(0xffffffffu, ls0, 1);
        ls0 += __shfl_xor_sync(0xffffffffu, ls0, 2);
        ls1 += __shfl_xor_sync(0xffffffffu, ls1, 1);
        ls1 += __shfl_xor_sync(0xffffffffu, ls1, 2);
        l0 = l0*cr0 + ls0;
        l1 = l1*cr1 + ls1;
        __syncwarp();   // P rows are warp-private; order stores before frag reads

        // ---- O += P V  (P split in regs, V pre-split) -----------------------
        #pragma unroll
        for (int ks = 0; ks < 8; ks++) {
            const int k8 = ks * 8;
            uint32_t ah[4], al[4];
            #pragma unroll
            for (int e = 0; e < 4; e++) {
                const int row = wr + g + (e & 1)*8;
                const int col = k8 + c + (e >> 1)*4;
                tf32_split(Ps[row*QSTR + col], ah[e], al[e]);
            }
            #pragma unroll
            for (int nt = 0; nt < 8; nt++) {
                uint32_t bh[2], bl[2];
                #pragma unroll
                for (int e = 0; e < 2; e++) {
                    const int kk = k8 + c + e*4;
                    bh[e] = __float_as_uint(Vh[kk*VSTR + nt*8 + g]);
                    bl[e] = __float_as_uint(Vl[kk*VSTR + nt*8 + g]);
                }
                mma_tf32(o[nt], ah, bh);
                mma_tf32(o[nt], ah, bl);
                mma_tf32(o[nt], al, bh);
            }
        }
    }

    // epilogue: normalize, write [B,S,H*DK]
    const float inv0 = 1.f / l0, inv1 = 1.f / l1;
    const int r0 = q0 + wr + g, r1 = r0 + 8;
    #pragma unroll
    for (int nt = 0; nt < 8; nt++) {
        const int col = h*DK_ + nt*8 + c*2;
        *(float2*)(g_attn + ((size_t)b*S_ + r0)*D_ + col) =
            make_float2(o[nt][0]*inv0, o[nt][1]*inv0);
        *(float2*)(g_attn + ((size_t)b*S_ + r1)*D_ + col) =
            make_float2(o[nt][2]*inv1, o[nt][3]*inv1);
    }
}

// ---------------- launch ------------------------------------------------------
extern "C" void kernel_launch(void* const* d_in, const int* in_sizes, int n_in,
                              void* d_out, int out_size)
{
    (void)in_sizes; (void)n_in; (void)out_size;
    const float* Q  = (const float*)d_in[0];
    const float* K  = (const float*)d_in[1];
    const float* V  = (const float*)d_in[2];
    const float* Wq = (const float*)d_in[3];
    const float* bq = (const float*)d_in[4];
    const float* Wk = (const float*)d_in[5];
    const float* bk = (const float*)d_in[6];
    const float* Wv = (const float*)d_in[7];
    const float* bv = (const float*)d_in[8];
    const float* Wo = (const float*)d_in[9];
    const float* bo = (const float*)d_in[10];
    float* out = (float*)d_out;

    float *qp, *kp, *vp, *ap;
    cudaGetSymbolAddress((void**)&qp, g_q);
    cudaGetSymbolAddress((void**)&kp, g_k);
    cudaGetSymbolAddress((void**)&vp, g_v);
    cudaGetSymbolAddress((void**)&ap, g_attn);

    cudaFuncSetAttribute(gemm_mma<0>, cudaFuncAttributeMaxDynamicSharedMemorySize, GEMM_SMEM_BYTES);
    cudaFuncSetAttribute(gemm_mma<1>, cudaFuncAttributeMaxDynamicSharedMemorySize, GEMM_SMEM_BYTES);
    cudaFuncSetAttribute(attn_mma,   cudaFuncAttributeMaxDynamicSharedMemorySize, ATTN_SMEM_BYTES);

    const dim3 gg(M_/128, D_/128);   // 32 x 8
    gemm_mma<1><<<gg, 256, GEMM_SMEM_BYTES>>>(Q, Wq, bq, qp);
    gemm_mma<1><<<gg, 256, GEMM_SMEM_BYTES>>>(K, Wk, bk, kp);
    gemm_mma<1><<<gg, 256, GEMM_SMEM_BYTES>>>(V, Wv, bv, vp);

    attn_mma<<<dim3(S_/128, H_, B_), 256, ATTN_SMEM_BYTES>>>();

    gemm_mma<0><<<gg, 256, GEMM_SMEM_BYTES>>>(ap, Wo, bo, out);
}